// round 14
// baseline (speedup 1.0000x reference)
#include <cuda_runtime.h>
#include <cuda_fp16.h>
#include <math.h>
#include <stdint.h>

// Problem constants
#define NT   4096   // B*T tokens
#define DD   1024   // model dim
#define HH   4096   // hidden dim
#define NE   8      // experts
#define TOPK 2

#define BM 128
#define BN 128
#define KC 32
#define STAGES 4

// w2 conversion slices handled by FC1's early-exit CTAs
#define NW4     (NE * HH * DD / 4)    // 8,388,608 float4
#define NSLICES 5920                  // min guaranteed exit-CTAs in k_fc1
#define SLICE   1418                  // 5920*1418 = 8,394,560 >= NW4

// ---------------- scratch (static device, no allocation) ----------------
__device__ int   g_cnt[NE];
__device__ int   g_tick;
__device__ int   g_tok [NE * NT];
__device__ float g_gw  [NE * NT];
__device__ int   g_hrow[NE * NT];

__device__ __half g_xf[(size_t)NT * DD];
__device__ __half g_w1f[(size_t)NE * DD * HH];
__device__ __half g_w2f[(size_t)NE * HH * DD];
__device__ __half g_hf[(size_t)NT * TOPK * HH];

// ---------------- PTX helpers (plain sm_103-safe) ----------------
__device__ __forceinline__ uint32_t smem_u32(const void* p) {
    uint32_t a;
    asm("{ .reg .u64 t; cvta.to.shared.u64 t, %1; cvt.u32.u64 %0, t; }" : "=r"(a) : "l"(p));
    return a;
}
__device__ __forceinline__ void cp16(uint32_t dst, const void* src, uint32_t srcsize) {
    asm volatile("cp.async.cg.shared.global [%0], [%1], 16, %2;"
                 :: "r"(dst), "l"(src), "r"(srcsize) : "memory");
}
#define CP_COMMIT()  asm volatile("cp.async.commit_group;" ::: "memory")
#define CP_WAIT1()   asm volatile("cp.async.wait_group 1;" ::: "memory")
#define CP_WAIT0()   asm volatile("cp.async.wait_group 0;" ::: "memory")

__device__ __forceinline__ void ldsm4(uint32_t* r, uint32_t addr) {
    asm volatile("ldmatrix.sync.aligned.m8n8.x4.shared.b16 {%0,%1,%2,%3}, [%4];"
                 : "=r"(r[0]), "=r"(r[1]), "=r"(r[2]), "=r"(r[3]) : "r"(addr));
}
__device__ __forceinline__ void ldsm4t(uint32_t* r, uint32_t addr) {
    asm volatile("ldmatrix.sync.aligned.m8n8.x4.trans.shared.b16 {%0,%1,%2,%3}, [%4];"
                 : "=r"(r[0]), "=r"(r[1]), "=r"(r[2]), "=r"(r[3]) : "r"(addr));
}
__device__ __forceinline__ void mma16816(float* d, const uint32_t* a, uint32_t b0, uint32_t b1) {
    asm volatile("mma.sync.aligned.m16n8k16.row.col.f32.f16.f16.f32 "
                 "{%0,%1,%2,%3}, {%4,%5,%6,%7}, {%8,%9}, {%0,%1,%2,%3};"
                 : "+f"(d[0]), "+f"(d[1]), "+f"(d[2]), "+f"(d[3])
                 : "r"(a[0]), "r"(a[1]), "r"(a[2]), "r"(a[3]), "r"(b0), "r"(b1));
}
__device__ __forceinline__ void red_add(float* p, float v) {
    asm volatile("red.global.add.f32 [%0], %1;" :: "l"(p), "f"(v) : "memory");
}

// ---------------- SMEM layout ----------------
#define AST 80
#define BST 272
#define OFF_TOK  0
#define OFF_HR   512
#define OFF_GWS  1024
#define OFF_TILE 1536
#define A_OFF 0
#define B_OFF 10240
#define BUF_SZ 18944
#define SMEM_SZ (OFF_TILE + STAGES * BUF_SZ)   // 77312

__device__ __forceinline__ void conv4(const float* __restrict__ src,
                                      __half* __restrict__ dst, int i) {
    float4 v = ((const float4*)src)[i];
    __half2 a = __floats2half2_rn(v.x, v.y);
    __half2 b = __floats2half2_rn(v.z, v.w);
    ((uint2*)dst)[i] = make_uint2(*(uint32_t*)&a, *(uint32_t*)&b);
}

// ---------------- fused prepass: gate + conv(x) + conv(w1) ----------------
#define NB_GATE  (NT / 8)                   // 512
#define NB_CX    (NT * DD / 4 / 256)        // 4096
#define NB_CW    (NE * DD * HH / 4 / 256)   // 32768
#define NB_TOTAL (NB_GATE + NB_CX + NB_CW)

__global__ void k_prepass(const float* __restrict__ x,
                          const float* __restrict__ gw,
                          const float* __restrict__ gb,
                          const float* __restrict__ w1) {
    int b = blockIdx.x;
    int tid = threadIdx.x;
    if (b < NB_GATE) {
        int lane = tid & 31;
        int tok = b * 8 + (tid >> 5);
        const float* xr = x + (size_t)tok * DD;
        float acc[NE];
#pragma unroll
        for (int e = 0; e < NE; e++) acc[e] = 0.0f;
        for (int d = lane; d < DD; d += 32) {
            float xv = xr[d];
#pragma unroll
            for (int e = 0; e < NE; e++) acc[e] += xv * gw[d * NE + e];
        }
#pragma unroll
        for (int e = 0; e < NE; e++) {
#pragma unroll
            for (int o = 16; o > 0; o >>= 1)
                acc[e] += __shfl_xor_sync(0xffffffffu, acc[e], o);
        }
        if (lane == 0) {
            float z[NE]; float m = -1e30f;
#pragma unroll
            for (int e = 0; e < NE; e++) { z[e] = acc[e] + gb[e]; m = fmaxf(m, z[e]); }
            float s = 0.0f;
#pragma unroll
            for (int e = 0; e < NE; e++) { z[e] = expf(z[e] - m); s += z[e]; }
            int i1 = 0;
#pragma unroll
            for (int e = 1; e < NE; e++) if (z[e] > z[i1]) i1 = e;
            int i2 = (i1 == 0) ? 1 : 0;
#pragma unroll
            for (int e = 0; e < NE; e++) if (e != i1 && z[e] > z[i2]) i2 = e;
            float inv = 1.0f / s;
            int es[2] = { i1, i2 };
#pragma unroll
            for (int k = 0; k < TOPK; k++) {
                int e = es[k];
                int slot = atomicAdd(&g_cnt[e], 1);
                g_tok [e * NT + slot] = tok;
                g_gw  [e * NT + slot] = z[e] * inv;
                g_hrow[e * NT + slot] = tok * TOPK + k;
            }
        }
    } else if (b < NB_GATE + NB_CX) {
        conv4(x, g_xf, (b - NB_GATE) * 256 + tid);
    } else {
        conv4(w1, g_w1f, (b - NB_GATE - NB_CX) * 256 + tid);
    }
}

// ---------------- tile fill (cp.async) ----------------
__device__ __forceinline__ void fill_tiles(uint32_t tb, int tid,
                                           const __half* __restrict__ A, int a_ld,
                                           const int* rows,
                                           const __half* __restrict__ B, int b_ld,
                                           int n0, int k0) {
#pragma unroll
    for (int i = 0; i < 2; i++) {
        int id = tid + i * 256;
        int r = id >> 2, c = id & 3;
        int t = rows[r];
        size_t off = (size_t)(t < 0 ? 0 : t) * a_ld + k0 + c * 8;
        cp16(tb + A_OFF + r * AST + c * 16, A + off, (t < 0) ? 0u : 16u);
    }
#pragma unroll
    for (int i = 0; i < 2; i++) {
        int id = tid + i * 256;
        int r = id >> 4, c = id & 15;
        size_t off = (size_t)(k0 + r) * b_ld + n0 + c * 8;
        cp16(tb + B_OFF + r * BST + c * 16, B + off, 16u);
    }
}

// ---------------- mma mainloop for one 32-K chunk ----------------
__device__ __forceinline__ void compute_chunk(uint32_t tb, int lane, int wm, int wn,
                                              float acc[4][4][4]) {
    int t  = lane >> 3;
    int lr = lane & 7;
#pragma unroll
    for (int k16 = 0; k16 < KC; k16 += 16) {
        uint32_t a[4][4];
#pragma unroll
        for (int mt = 0; mt < 4; mt++) {
            uint32_t addr = tb + A_OFF + (uint32_t)(wm + mt * 16 + (t & 1) * 8 + lr) * AST
                          + (uint32_t)(k16 + (t >> 1) * 8) * 2;
            ldsm4(a[mt], addr);
        }
#pragma unroll
        for (int j = 0; j < 2; j++) {
            uint32_t b[4];
            uint32_t addr = tb + B_OFF + (uint32_t)(k16 + (t & 1) * 8 + lr) * BST
                          + (uint32_t)(wn + j * 16 + (t >> 1) * 8) * 2;
            ldsm4t(b, addr);
#pragma unroll
            for (int mt = 0; mt < 4; mt++) {
                mma16816(acc[mt][j * 2 + 0], a[mt], b[0], b[1]);
                mma16816(acc[mt][j * 2 + 1], a[mt], b[2], b[3]);
            }
        }
    }
}

__device__ __forceinline__ void gemm_mainloop(uint32_t sb, int tid, int lane, int wm, int wn,
                                              const __half* __restrict__ A, int a_ld,
                                              const int* rows,
                                              const __half* __restrict__ B, int b_ld,
                                              int n0, int NCH, float acc[4][4][4]) {
#pragma unroll
    for (int s = 0; s < STAGES - 1; s++) {
        fill_tiles(sb + OFF_TILE + s * BUF_SZ, tid, A, a_ld, rows, B, b_ld, n0, s * KC);
        CP_COMMIT();
    }
    int stage = 0;
    for (int c = 0; c < NCH; c++) {
        if (c + 1 < NCH) CP_WAIT1(); else CP_WAIT0();
        __syncthreads();
        if (c + STAGES - 1 < NCH) {
            int fs = stage + STAGES - 1; if (fs >= STAGES) fs -= STAGES;
            fill_tiles(sb + OFF_TILE + fs * BUF_SZ, tid, A, a_ld, rows, B, b_ld, n0,
                       (c + STAGES - 1) * KC);
            CP_COMMIT();
        }
        compute_chunk(sb + OFF_TILE + stage * BUF_SZ, lane, wm, wn, acc);
        stage++; if (stage >= STAGES) stage = 0;
    }
}

// ---------------- FC1 (+ hidden w2 conversion in exit-CTAs) ----------------
__global__ void __launch_bounds__(256, 2)
k_fc1(const float* __restrict__ b1, const float* __restrict__ w2) {
    int e = blockIdx.z;
    int cnt = g_cnt[e];
    int m0 = blockIdx.y * BM;
    int tid = threadIdx.x;

    if (m0 >= cnt) {
        // conversion duty: grab a ticket, convert a slice of w2
        __shared__ int s_tick;
        if (tid == 0) s_tick = atomicAdd(&g_tick, 1);
        __syncthreads();
        int t = s_tick;
        if (t < NSLICES) {
            int beg = t * SLICE;
            int end = beg + SLICE; if (end > NW4) end = NW4;
            for (int i = beg + tid; i < end; i += 256) conv4(w2, g_w2f, i);
        }
        return;
    }
    int n0 = blockIdx.x * BN;

    extern __shared__ char smem[];
    uint32_t sb = smem_u32(smem);
    int wid = tid >> 5, lane = tid & 31;
    int* toks  = (int*)(smem + OFF_TOK);
    int* hrows = (int*)(smem + OFF_HR);
    if (tid < BM) {
        int s = m0 + tid;
        toks [tid] = (s < cnt) ? g_tok [e * NT + s] : -1;
        hrows[tid] = (s < cnt) ? g_hrow[e * NT + s] : -1;
    }
    __syncthreads();

    const __half* W = g_w1f + (size_t)e * DD * HH;

    float acc[4][4][4];
#pragma unroll
    for (int a = 0; a < 4; a++)
#pragma unroll
        for (int b = 0; b < 4; b++)
#pragma unroll
            for (int c = 0; c < 4; c++) acc[a][b][c] = 0.0f;

    int wm = (wid >> 2) * 64, wn = (wid & 3) * 32;

    gemm_mainloop(sb, tid, lane, wm, wn, g_xf, DD, toks, W, HH, n0, DD / KC, acc);

    const float* bb = b1 + (size_t)e * HH + n0;
#pragma unroll
    for (int mt = 0; mt < 4; mt++) {
#pragma unroll
        for (int nt = 0; nt < 4; nt++) {
            int col = wn + nt * 8 + (lane & 3) * 2;
            float bv0 = bb[col], bv1 = bb[col + 1];
#pragma unroll
            for (int half = 0; half < 2; half++) {
                int li = wm + mt * 16 + (lane >> 2) + half * 8;
                int hr = hrows[li];
                if (hr < 0) continue;
                float h0 = fmaxf(acc[mt][nt][half * 2 + 0] + bv0, 0.0f);
                float h1 = fmaxf(acc[mt][nt][half * 2 + 1] + bv1, 0.0f);
                __half2 hp = __floats2half2_rn(h0, h1);
                *(uint32_t*)(g_hf + (size_t)hr * HH + n0 + col) = *(uint32_t*)&hp;
            }
        }
    }
}

// ---------------- FC2: out[tok] += gate * (h[hrow] @ w2[e] + b2[e]) via RED ----------------
__global__ void __launch_bounds__(256, 2)
k_fc2(const float* __restrict__ b2, float* __restrict__ out) {
    int e = blockIdx.z;
    int cnt = g_cnt[e];
    int m0 = blockIdx.y * BM;
    if (m0 >= cnt) return;
    int n0 = blockIdx.x * BN;

    extern __shared__ char smem[];
    uint32_t sb = smem_u32(smem);
    int tid = threadIdx.x, wid = tid >> 5, lane = tid & 31;
    int*   toks  = (int*)(smem + OFF_TOK);
    int*   hrows = (int*)(smem + OFF_HR);
    float* gws   = (float*)(smem + OFF_GWS);
    if (tid < BM) {
        int s = m0 + tid;
        toks [tid] = (s < cnt) ? g_tok [e * NT + s] : -1;
        hrows[tid] = (s < cnt) ? g_hrow[e * NT + s] : -1;
        gws  [tid] = (s < cnt) ? g_gw  [e * NT + s] : 0.0f;
    }
    __syncthreads();

    const __half* W = g_w2f + (size_t)e * HH * DD;

    float acc[4][4][4];
#pragma unroll
    for (int a = 0; a < 4; a++)
#pragma unroll
        for (int b = 0; b < 4; b++)
#pragma unroll
            for (int c = 0; c < 4; c++) acc[a][b][c] = 0.0f;

    int wm = (wid >> 2) * 64, wn = (wid & 3) * 32;

    gemm_mainloop(sb, tid, lane, wm, wn, g_hf, HH, hrows, W, DD, n0, HH / KC, acc);

    const float* bb = b2 + (size_t)e * DD + n0;
#pragma unroll
    for (int mt = 0; mt < 4; mt++) {
#pragma unroll
        for (int nt = 0; nt < 4; nt++) {
            int col = wn + nt * 8 + (lane & 3) * 2;
            float bv0 = bb[col], bv1 = bb[col + 1];
#pragma unroll
            for (int half = 0; half < 2; half++) {
                int li = wm + mt * 16 + (lane >> 2) + half * 8;
                int tok = toks[li];
                if (tok < 0) continue;
                float g = gws[li];
                float* op = out + (size_t)tok * DD + n0 + col;
                red_add(op + 0, g * (acc[mt][nt][half * 2 + 0] + bv0));
                red_add(op + 1, g * (acc[mt][nt][half * 2 + 1] + bv1));
            }
        }
    }
}

// ---------------- launch ----------------
extern "C" void kernel_launch(void* const* d_in, const int* in_sizes, int n_in,
                              void* d_out, int out_size) {
    const float* x  = (const float*)d_in[0];
    const float* gw = (const float*)d_in[1];
    const float* gb = (const float*)d_in[2];
    const float* w1 = (const float*)d_in[3];
    const float* b1 = (const float*)d_in[4];
    const float* w2 = (const float*)d_in[5];
    const float* b2 = (const float*)d_in[6];
    float* out = (float*)d_out;

    cudaFuncSetAttribute(k_fc1, cudaFuncAttributeMaxDynamicSharedMemorySize, SMEM_SZ);
    cudaFuncSetAttribute(k_fc2, cudaFuncAttributeMaxDynamicSharedMemorySize, SMEM_SZ);

    void* cntp; cudaGetSymbolAddress(&cntp, g_cnt);
    void* tickp; cudaGetSymbolAddress(&tickp, g_tick);
    cudaMemsetAsync(cntp, 0, NE * sizeof(int));
    cudaMemsetAsync(tickp, 0, sizeof(int));
    cudaMemsetAsync(out, 0, (size_t)out_size * sizeof(float));

    k_prepass<<<NB_TOTAL, 256>>>(x, gw, gb, w1);

    dim3 g1(HH / BN, NT / BM, NE);   // 32 x 32 x 8
    k_fc1<<<g1, 256, SMEM_SZ>>>(b1, w2);

    dim3 g2(DD / BN, NT / BM, NE);   // 8 x 32 x 8
    k_fc2<<<g2, 256, SMEM_SZ>>>(b2, out);
}

// round 15
// speedup vs baseline: 1.0384x; 1.0384x over previous
#include <cuda_runtime.h>
#include <cuda_fp16.h>
#include <math.h>
#include <stdint.h>

// Problem constants
#define NT   4096   // B*T tokens
#define DD   1024   // model dim
#define HH   4096   // hidden dim
#define NE   8      // experts
#define TOPK 2

#define BM 128
#define BN 128
#define KC 32
#define STAGES 4

// ---------------- scratch (static device, no allocation) ----------------
__device__ int   g_cnt[NE];
__device__ int   g_tok [NE * NT];
__device__ float g_gw  [NE * NT];
__device__ int   g_hrow[NE * NT];

__device__ __half g_xf[(size_t)NT * DD];
__device__ __half g_w1f[(size_t)NE * DD * HH];
__device__ __half g_w2f[(size_t)NE * HH * DD];
__device__ __half g_hf[(size_t)NT * TOPK * HH];

// ---------------- PTX helpers (plain sm_103-safe) ----------------
__device__ __forceinline__ uint32_t smem_u32(const void* p) {
    uint32_t a;
    asm("{ .reg .u64 t; cvta.to.shared.u64 t, %1; cvt.u32.u64 %0, t; }" : "=r"(a) : "l"(p));
    return a;
}
__device__ __forceinline__ void cp16(uint32_t dst, const void* src, uint32_t srcsize) {
    asm volatile("cp.async.cg.shared.global [%0], [%1], 16, %2;"
                 :: "r"(dst), "l"(src), "r"(srcsize) : "memory");
}
#define CP_COMMIT()  asm volatile("cp.async.commit_group;" ::: "memory")
#define CP_WAIT1()   asm volatile("cp.async.wait_group 1;" ::: "memory")
#define CP_WAIT0()   asm volatile("cp.async.wait_group 0;" ::: "memory")

__device__ __forceinline__ void ldsm4(uint32_t* r, uint32_t addr) {
    asm volatile("ldmatrix.sync.aligned.m8n8.x4.shared.b16 {%0,%1,%2,%3}, [%4];"
                 : "=r"(r[0]), "=r"(r[1]), "=r"(r[2]), "=r"(r[3]) : "r"(addr));
}
__device__ __forceinline__ void ldsm4t(uint32_t* r, uint32_t addr) {
    asm volatile("ldmatrix.sync.aligned.m8n8.x4.trans.shared.b16 {%0,%1,%2,%3}, [%4];"
                 : "=r"(r[0]), "=r"(r[1]), "=r"(r[2]), "=r"(r[3]) : "r"(addr));
}
__device__ __forceinline__ void mma16816(float* d, const uint32_t* a, uint32_t b0, uint32_t b1) {
    asm volatile("mma.sync.aligned.m16n8k16.row.col.f32.f16.f16.f32 "
                 "{%0,%1,%2,%3}, {%4,%5,%6,%7}, {%8,%9}, {%0,%1,%2,%3};"
                 : "+f"(d[0]), "+f"(d[1]), "+f"(d[2]), "+f"(d[3])
                 : "r"(a[0]), "r"(a[1]), "r"(a[2]), "r"(a[3]), "r"(b0), "r"(b1));
}
__device__ __forceinline__ void red_add(float* p, float v) {
    asm volatile("red.global.add.f32 [%0], %1;" :: "l"(p), "f"(v) : "memory");
}

// ---------------- SMEM layout ----------------
#define AST 80
#define BST 272
#define OFF_TOK  0
#define OFF_HR   512
#define OFF_GWS  1024
#define OFF_TILE 1536
#define A_OFF 0
#define B_OFF 10240
#define BUF_SZ 18944
#define SMEM_SZ (OFF_TILE + STAGES * BUF_SZ)   // 77312

// ---------------- fused prepass: gate + conv(x,w1,w2), MLP=2 convs ----------------
#define NB_GATE  (NT / 8)                    // 512
#define NB_CX    (NT * DD / 4 / 512)         // 2048 (2 float4/thread)
#define NB_CW    (NE * DD * HH / 4 / 512)    // 16384
#define NB_TOTAL (NB_GATE + NB_CX + 2 * NB_CW)

__device__ __forceinline__ void conv4x2(const float* __restrict__ src,
                                        __half* __restrict__ dst, int i0) {
    int i1 = i0 + 256;
    float4 v0 = ((const float4*)src)[i0];
    float4 v1 = ((const float4*)src)[i1];
    __half2 a0 = __floats2half2_rn(v0.x, v0.y), b0 = __floats2half2_rn(v0.z, v0.w);
    __half2 a1 = __floats2half2_rn(v1.x, v1.y), b1 = __floats2half2_rn(v1.z, v1.w);
    ((uint2*)dst)[i0] = make_uint2(*(uint32_t*)&a0, *(uint32_t*)&b0);
    ((uint2*)dst)[i1] = make_uint2(*(uint32_t*)&a1, *(uint32_t*)&b1);
}

__global__ void k_prepass(const float* __restrict__ x,
                          const float* __restrict__ gw,
                          const float* __restrict__ gb,
                          const float* __restrict__ w1,
                          const float* __restrict__ w2) {
    int b = blockIdx.x;
    int tid = threadIdx.x;
    if (b < NB_GATE) {
        // ---- gating: one warp per token ----
        int lane = tid & 31;
        int tok = b * 8 + (tid >> 5);
        const float* xr = x + (size_t)tok * DD;
        float acc[NE];
#pragma unroll
        for (int e = 0; e < NE; e++) acc[e] = 0.0f;
        for (int d = lane; d < DD; d += 32) {
            float xv = xr[d];
#pragma unroll
            for (int e = 0; e < NE; e++) acc[e] += xv * gw[d * NE + e];
        }
#pragma unroll
        for (int e = 0; e < NE; e++) {
#pragma unroll
            for (int o = 16; o > 0; o >>= 1)
                acc[e] += __shfl_xor_sync(0xffffffffu, acc[e], o);
        }
        if (lane == 0) {
            float z[NE]; float m = -1e30f;
#pragma unroll
            for (int e = 0; e < NE; e++) { z[e] = acc[e] + gb[e]; m = fmaxf(m, z[e]); }
            float s = 0.0f;
#pragma unroll
            for (int e = 0; e < NE; e++) { z[e] = expf(z[e] - m); s += z[e]; }
            int i1 = 0;
#pragma unroll
            for (int e = 1; e < NE; e++) if (z[e] > z[i1]) i1 = e;
            int i2 = (i1 == 0) ? 1 : 0;
#pragma unroll
            for (int e = 0; e < NE; e++) if (e != i1 && z[e] > z[i2]) i2 = e;
            float inv = 1.0f / s;
            int es[2] = { i1, i2 };
#pragma unroll
            for (int k = 0; k < TOPK; k++) {
                int e = es[k];
                int slot = atomicAdd(&g_cnt[e], 1);
                g_tok [e * NT + slot] = tok;
                g_gw  [e * NT + slot] = z[e] * inv;
                g_hrow[e * NT + slot] = tok * TOPK + k;
            }
        }
    } else if (b < NB_GATE + NB_CX) {
        conv4x2(x, g_xf, (b - NB_GATE) * 512 + tid);
    } else if (b < NB_GATE + NB_CX + NB_CW) {
        conv4x2(w1, g_w1f, (b - NB_GATE - NB_CX) * 512 + tid);
    } else {
        conv4x2(w2, g_w2f, (b - NB_GATE - NB_CX - NB_CW) * 512 + tid);
    }
}

// ---------------- tile fill (cp.async) ----------------
__device__ __forceinline__ void fill_tiles(uint32_t tb, int tid,
                                           const __half* __restrict__ A, int a_ld,
                                           const int* rows,
                                           const __half* __restrict__ B, int b_ld,
                                           int n0, int k0) {
#pragma unroll
    for (int i = 0; i < 2; i++) {
        int id = tid + i * 256;
        int r = id >> 2, c = id & 3;
        int t = rows[r];
        size_t off = (size_t)(t < 0 ? 0 : t) * a_ld + k0 + c * 8;
        cp16(tb + A_OFF + r * AST + c * 16, A + off, (t < 0) ? 0u : 16u);
    }
#pragma unroll
    for (int i = 0; i < 2; i++) {
        int id = tid + i * 256;
        int r = id >> 4, c = id & 15;
        size_t off = (size_t)(k0 + r) * b_ld + n0 + c * 8;
        cp16(tb + B_OFF + r * BST + c * 16, B + off, 16u);
    }
}

// ---------------- mma mainloop for one 32-K chunk ----------------
__device__ __forceinline__ void compute_chunk(uint32_t tb, int lane, int wm, int wn,
                                              float acc[4][4][4]) {
    int t  = lane >> 3;
    int lr = lane & 7;
#pragma unroll
    for (int k16 = 0; k16 < KC; k16 += 16) {
        uint32_t a[4][4];
#pragma unroll
        for (int mt = 0; mt < 4; mt++) {
            uint32_t addr = tb + A_OFF + (uint32_t)(wm + mt * 16 + (t & 1) * 8 + lr) * AST
                          + (uint32_t)(k16 + (t >> 1) * 8) * 2;
            ldsm4(a[mt], addr);
        }
#pragma unroll
        for (int j = 0; j < 2; j++) {
            uint32_t b[4];
            uint32_t addr = tb + B_OFF + (uint32_t)(k16 + (t & 1) * 8 + lr) * BST
                          + (uint32_t)(wn + j * 16 + (t >> 1) * 8) * 2;
            ldsm4t(b, addr);
#pragma unroll
            for (int mt = 0; mt < 4; mt++) {
                mma16816(acc[mt][j * 2 + 0], a[mt], b[0], b[1]);
                mma16816(acc[mt][j * 2 + 1], a[mt], b[2], b[3]);
            }
        }
    }
}

__device__ __forceinline__ void gemm_mainloop(uint32_t sb, int tid, int lane, int wm, int wn,
                                              const __half* __restrict__ A, int a_ld,
                                              const int* rows,
                                              const __half* __restrict__ B, int b_ld,
                                              int n0, int NCH, float acc[4][4][4]) {
#pragma unroll
    for (int s = 0; s < STAGES - 1; s++) {
        fill_tiles(sb + OFF_TILE + s * BUF_SZ, tid, A, a_ld, rows, B, b_ld, n0, s * KC);
        CP_COMMIT();
    }
    int stage = 0;
    for (int c = 0; c < NCH; c++) {
        if (c + 1 < NCH) CP_WAIT1(); else CP_WAIT0();
        __syncthreads();
        if (c + STAGES - 1 < NCH) {
            int fs = stage + STAGES - 1; if (fs >= STAGES) fs -= STAGES;
            fill_tiles(sb + OFF_TILE + fs * BUF_SZ, tid, A, a_ld, rows, B, b_ld, n0,
                       (c + STAGES - 1) * KC);
            CP_COMMIT();
        }
        compute_chunk(sb + OFF_TILE + stage * BUF_SZ, lane, wm, wn, acc);
        stage++; if (stage >= STAGES) stage = 0;
    }
}

// ---------------- FC1: h[hrow] = relu(x[tok] @ w1[e] + b1[e]) -> fp16 ----------------
__global__ void __launch_bounds__(256, 2)
k_fc1(const float* __restrict__ b1) {
    int e = blockIdx.z;
    int cnt = g_cnt[e];
    int m0 = blockIdx.y * BM;
    if (m0 >= cnt) return;
    int n0 = blockIdx.x * BN;

    extern __shared__ char smem[];
    uint32_t sb = smem_u32(smem);
    int tid = threadIdx.x, wid = tid >> 5, lane = tid & 31;
    int* toks  = (int*)(smem + OFF_TOK);
    int* hrows = (int*)(smem + OFF_HR);
    if (tid < BM) {
        int s = m0 + tid;
        toks [tid] = (s < cnt) ? g_tok [e * NT + s] : -1;
        hrows[tid] = (s < cnt) ? g_hrow[e * NT + s] : -1;
    }
    __syncthreads();

    const __half* W = g_w1f + (size_t)e * DD * HH;

    float acc[4][4][4];
#pragma unroll
    for (int a = 0; a < 4; a++)
#pragma unroll
        for (int b = 0; b < 4; b++)
#pragma unroll
            for (int c = 0; c < 4; c++) acc[a][b][c] = 0.0f;

    int wm = (wid >> 2) * 64, wn = (wid & 3) * 32;

    gemm_mainloop(sb, tid, lane, wm, wn, g_xf, DD, toks, W, HH, n0, DD / KC, acc);

    const float* bb = b1 + (size_t)e * HH + n0;
#pragma unroll
    for (int mt = 0; mt < 4; mt++) {
#pragma unroll
        for (int nt = 0; nt < 4; nt++) {
            int col = wn + nt * 8 + (lane & 3) * 2;
            float bv0 = bb[col], bv1 = bb[col + 1];
#pragma unroll
            for (int half = 0; half < 2; half++) {
                int li = wm + mt * 16 + (lane >> 2) + half * 8;
                int hr = hrows[li];
                if (hr < 0) continue;
                float h0 = fmaxf(acc[mt][nt][half * 2 + 0] + bv0, 0.0f);
                float h1 = fmaxf(acc[mt][nt][half * 2 + 1] + bv1, 0.0f);
                __half2 hp = __floats2half2_rn(h0, h1);
                *(uint32_t*)(g_hf + (size_t)hr * HH + n0 + col) = *(uint32_t*)&hp;
            }
        }
    }
}

// ---------------- FC2: out[tok] += gate * (h[hrow] @ w2[e] + b2[e]) via RED ----------------
__global__ void __launch_bounds__(256, 2)
k_fc2(const float* __restrict__ b2, float* __restrict__ out) {
    int e = blockIdx.z;
    int cnt = g_cnt[e];
    int m0 = blockIdx.y * BM;
    if (m0 >= cnt) return;
    int n0 = blockIdx.x * BN;

    extern __shared__ char smem[];
    uint32_t sb = smem_u32(smem);
    int tid = threadIdx.x, wid = tid >> 5, lane = tid & 31;
    int*   toks  = (int*)(smem + OFF_TOK);
    int*   hrows = (int*)(smem + OFF_HR);
    float* gws   = (float*)(smem + OFF_GWS);
    if (tid < BM) {
        int s = m0 + tid;
        toks [tid] = (s < cnt) ? g_tok [e * NT + s] : -1;
        hrows[tid] = (s < cnt) ? g_hrow[e * NT + s] : -1;
        gws  [tid] = (s < cnt) ? g_gw  [e * NT + s] : 0.0f;
    }
    __syncthreads();

    const __half* W = g_w2f + (size_t)e * HH * DD;

    float acc[4][4][4];
#pragma unroll
    for (int a = 0; a < 4; a++)
#pragma unroll
        for (int b = 0; b < 4; b++)
#pragma unroll
            for (int c = 0; c < 4; c++) acc[a][b][c] = 0.0f;

    int wm = (wid >> 2) * 64, wn = (wid & 3) * 32;

    gemm_mainloop(sb, tid, lane, wm, wn, g_hf, HH, hrows, W, DD, n0, HH / KC, acc);

    const float* bb = b2 + (size_t)e * DD + n0;
#pragma unroll
    for (int mt = 0; mt < 4; mt++) {
#pragma unroll
        for (int nt = 0; nt < 4; nt++) {
            int col = wn + nt * 8 + (lane & 3) * 2;
            float bv0 = bb[col], bv1 = bb[col + 1];
#pragma unroll
            for (int half = 0; half < 2; half++) {
                int li = wm + mt * 16 + (lane >> 2) + half * 8;
                int tok = toks[li];
                if (tok < 0) continue;
                float g = gws[li];
                float* op = out + (size_t)tok * DD + n0 + col;
                red_add(op + 0, g * (acc[mt][nt][half * 2 + 0] + bv0));
                red_add(op + 1, g * (acc[mt][nt][half * 2 + 1] + bv1));
            }
        }
    }
}

// ---------------- launch ----------------
extern "C" void kernel_launch(void* const* d_in, const int* in_sizes, int n_in,
                              void* d_out, int out_size) {
    const float* x  = (const float*)d_in[0];
    const float* gw = (const float*)d_in[1];
    const float* gb = (const float*)d_in[2];
    const float* w1 = (const float*)d_in[3];
    const float* b1 = (const float*)d_in[4];
    const float* w2 = (const float*)d_in[5];
    const float* b2 = (const float*)d_in[6];
    float* out = (float*)d_out;

    cudaFuncSetAttribute(k_fc1, cudaFuncAttributeMaxDynamicSharedMemorySize, SMEM_SZ);
    cudaFuncSetAttribute(k_fc2, cudaFuncAttributeMaxDynamicSharedMemorySize, SMEM_SZ);

    void* cntp; cudaGetSymbolAddress(&cntp, g_cnt);
    cudaMemsetAsync(cntp, 0, NE * sizeof(int));
    cudaMemsetAsync(out, 0, (size_t)out_size * sizeof(float));

    k_prepass<<<NB_TOTAL, 256>>>(x, gw, gb, w1, w2);

    dim3 g1(HH / BN, NT / BM, NE);   // 32 x 32 x 8
    k_fc1<<<g1, 256, SMEM_SZ>>>(b1);

    dim3 g2(DD / BN, NT / BM, NE);   // 8 x 32 x 8
    k_fc2<<<g2, 256, SMEM_SZ>>>(b2, out);
}

// round 16
// speedup vs baseline: 1.0511x; 1.0123x over previous
#include <cuda_runtime.h>
#include <cuda_fp16.h>
#include <math.h>
#include <stdint.h>

// Problem constants
#define NT   4096   // B*T tokens
#define DD   1024   // model dim
#define HH   4096   // hidden dim
#define NE   8      // experts
#define TOPK 2

#define BM 128
#define BN 128
#define KC 32
#define STAGES 4

#define NN1 (HH / BN)   // 32 n-blocks in FC1
#define NN2 (DD / BN)   // 8  n-blocks in FC2

// ---------------- scratch (static device, no allocation) ----------------
__device__ int   g_cnt[NE];
__device__ int   g_tok [NE * NT];
__device__ float g_gw  [NE * NT];
__device__ int   g_hrow[NE * NT];

__device__ __half g_xf[(size_t)NT * DD];
__device__ __half g_w1f[(size_t)NE * DD * HH];
__device__ __half g_w2f[(size_t)NE * HH * DD];
__device__ __half g_hf[(size_t)NT * TOPK * HH];

// ---------------- PTX helpers (plain sm_103-safe) ----------------
__device__ __forceinline__ uint32_t smem_u32(const void* p) {
    uint32_t a;
    asm("{ .reg .u64 t; cvta.to.shared.u64 t, %1; cvt.u32.u64 %0, t; }" : "=r"(a) : "l"(p));
    return a;
}
__device__ __forceinline__ void cp16(uint32_t dst, const void* src, uint32_t srcsize) {
    asm volatile("cp.async.cg.shared.global [%0], [%1], 16, %2;"
                 :: "r"(dst), "l"(src), "r"(srcsize) : "memory");
}
#define CP_COMMIT()  asm volatile("cp.async.commit_group;" ::: "memory")
#define CP_WAIT1()   asm volatile("cp.async.wait_group 1;" ::: "memory")
#define CP_WAIT0()   asm volatile("cp.async.wait_group 0;" ::: "memory")

__device__ __forceinline__ void ldsm4(uint32_t* r, uint32_t addr) {
    asm volatile("ldmatrix.sync.aligned.m8n8.x4.shared.b16 {%0,%1,%2,%3}, [%4];"
                 : "=r"(r[0]), "=r"(r[1]), "=r"(r[2]), "=r"(r[3]) : "r"(addr));
}
__device__ __forceinline__ void ldsm4t(uint32_t* r, uint32_t addr) {
    asm volatile("ldmatrix.sync.aligned.m8n8.x4.trans.shared.b16 {%0,%1,%2,%3}, [%4];"
                 : "=r"(r[0]), "=r"(r[1]), "=r"(r[2]), "=r"(r[3]) : "r"(addr));
}
__device__ __forceinline__ void mma16816(float* d, const uint32_t* a, uint32_t b0, uint32_t b1) {
    asm volatile("mma.sync.aligned.m16n8k16.row.col.f32.f16.f16.f32 "
                 "{%0,%1,%2,%3}, {%4,%5,%6,%7}, {%8,%9}, {%0,%1,%2,%3};"
                 : "+f"(d[0]), "+f"(d[1]), "+f"(d[2]), "+f"(d[3])
                 : "r"(a[0]), "r"(a[1]), "r"(a[2]), "r"(a[3]), "r"(b0), "r"(b1));
}
__device__ __forceinline__ void red_add(float* p, float v) {
    asm volatile("red.global.add.f32 [%0], %1;" :: "l"(p), "f"(v) : "memory");
}

// ---------------- SMEM layout ----------------
#define AST 80
#define BST 272
#define OFF_TOK  0
#define OFF_HR   512
#define OFF_GWS  1024
#define OFF_TILE 1536
#define A_OFF 0
#define B_OFF 10240
#define BUF_SZ 18944
#define SMEM_SZ (OFF_TILE + STAGES * BUF_SZ)   // 77312

// ---------------- fused prepass: gate + conv(x,w1,w2), MLP=4 convs ----------------
#define NB_GATE  (NT / 8)                    // 512
#define NB_CX    (NT * DD / 4 / 1024)        // 1024 (4 float4/thread)
#define NB_CW    (NE * DD * HH / 4 / 1024)   // 8192
#define NB_TOTAL (NB_GATE + NB_CX + 2 * NB_CW)

__device__ __forceinline__ void conv4x4(const float* __restrict__ src,
                                        __half* __restrict__ dst, int i0) {
    float4 v0 = ((const float4*)src)[i0];
    float4 v1 = ((const float4*)src)[i0 + 256];
    float4 v2 = ((const float4*)src)[i0 + 512];
    float4 v3 = ((const float4*)src)[i0 + 768];
    __half2 a0 = __floats2half2_rn(v0.x, v0.y), b0 = __floats2half2_rn(v0.z, v0.w);
    __half2 a1 = __floats2half2_rn(v1.x, v1.y), b1 = __floats2half2_rn(v1.z, v1.w);
    __half2 a2 = __floats2half2_rn(v2.x, v2.y), b2 = __floats2half2_rn(v2.z, v2.w);
    __half2 a3 = __floats2half2_rn(v3.x, v3.y), b3 = __floats2half2_rn(v3.z, v3.w);
    ((uint2*)dst)[i0      ] = make_uint2(*(uint32_t*)&a0, *(uint32_t*)&b0);
    ((uint2*)dst)[i0 + 256] = make_uint2(*(uint32_t*)&a1, *(uint32_t*)&b1);
    ((uint2*)dst)[i0 + 512] = make_uint2(*(uint32_t*)&a2, *(uint32_t*)&b2);
    ((uint2*)dst)[i0 + 768] = make_uint2(*(uint32_t*)&a3, *(uint32_t*)&b3);
}

__global__ void k_prepass(const float* __restrict__ x,
                          const float* __restrict__ gw,
                          const float* __restrict__ gb,
                          const float* __restrict__ w1,
                          const float* __restrict__ w2) {
    int b = blockIdx.x;
    int tid = threadIdx.x;
    if (b < NB_GATE) {
        int lane = tid & 31;
        int tok = b * 8 + (tid >> 5);
        const float* xr = x + (size_t)tok * DD;
        float acc[NE];
#pragma unroll
        for (int e = 0; e < NE; e++) acc[e] = 0.0f;
        for (int d = lane; d < DD; d += 32) {
            float xv = xr[d];
#pragma unroll
            for (int e = 0; e < NE; e++) acc[e] += xv * gw[d * NE + e];
        }
#pragma unroll
        for (int e = 0; e < NE; e++) {
#pragma unroll
            for (int o = 16; o > 0; o >>= 1)
                acc[e] += __shfl_xor_sync(0xffffffffu, acc[e], o);
        }
        if (lane == 0) {
            float z[NE]; float m = -1e30f;
#pragma unroll
            for (int e = 0; e < NE; e++) { z[e] = acc[e] + gb[e]; m = fmaxf(m, z[e]); }
            float s = 0.0f;
#pragma unroll
            for (int e = 0; e < NE; e++) { z[e] = expf(z[e] - m); s += z[e]; }
            int i1 = 0;
#pragma unroll
            for (int e = 1; e < NE; e++) if (z[e] > z[i1]) i1 = e;
            int i2 = (i1 == 0) ? 1 : 0;
#pragma unroll
            for (int e = 0; e < NE; e++) if (e != i1 && z[e] > z[i2]) i2 = e;
            float inv = 1.0f / s;
            int es[2] = { i1, i2 };
#pragma unroll
            for (int k = 0; k < TOPK; k++) {
                int e = es[k];
                int slot = atomicAdd(&g_cnt[e], 1);
                g_tok [e * NT + slot] = tok;
                g_gw  [e * NT + slot] = z[e] * inv;
                g_hrow[e * NT + slot] = tok * TOPK + k;
            }
        }
    } else if (b < NB_GATE + NB_CX) {
        conv4x4(x, g_xf, (b - NB_GATE) * 1024 + tid);
    } else if (b < NB_GATE + NB_CX + NB_CW) {
        conv4x4(w1, g_w1f, (b - NB_GATE - NB_CX) * 1024 + tid);
    } else {
        conv4x4(w2, g_w2f, (b - NB_GATE - NB_CX - NB_CW) * 1024 + tid);
    }
}

// ---------------- tile fill (cp.async) ----------------
__device__ __forceinline__ void fill_tiles(uint32_t tb, int tid,
                                           const __half* __restrict__ A, int a_ld,
                                           const int* rows,
                                           const __half* __restrict__ B, int b_ld,
                                           int n0, int k0) {
#pragma unroll
    for (int i = 0; i < 2; i++) {
        int id = tid + i * 256;
        int r = id >> 2, c = id & 3;
        int t = rows[r];
        size_t off = (size_t)(t < 0 ? 0 : t) * a_ld + k0 + c * 8;
        cp16(tb + A_OFF + r * AST + c * 16, A + off, (t < 0) ? 0u : 16u);
    }
#pragma unroll
    for (int i = 0; i < 2; i++) {
        int id = tid + i * 256;
        int r = id >> 4, c = id & 15;
        size_t off = (size_t)(k0 + r) * b_ld + n0 + c * 8;
        cp16(tb + B_OFF + r * BST + c * 16, B + off, 16u);
    }
}

// ---------------- mma mainloop for one 32-K chunk ----------------
__device__ __forceinline__ void compute_chunk(uint32_t tb, int lane, int wm, int wn,
                                              float acc[4][4][4]) {
    int t  = lane >> 3;
    int lr = lane & 7;
#pragma unroll
    for (int k16 = 0; k16 < KC; k16 += 16) {
        uint32_t a[4][4];
#pragma unroll
        for (int mt = 0; mt < 4; mt++) {
            uint32_t addr = tb + A_OFF + (uint32_t)(wm + mt * 16 + (t & 1) * 8 + lr) * AST
                          + (uint32_t)(k16 + (t >> 1) * 8) * 2;
            ldsm4(a[mt], addr);
        }
#pragma unroll
        for (int j = 0; j < 2; j++) {
            uint32_t b[4];
            uint32_t addr = tb + B_OFF + (uint32_t)(k16 + (t & 1) * 8 + lr) * BST
                          + (uint32_t)(wn + j * 16 + (t >> 1) * 8) * 2;
            ldsm4t(b, addr);
#pragma unroll
            for (int mt = 0; mt < 4; mt++) {
                mma16816(acc[mt][j * 2 + 0], a[mt], b[0], b[1]);
                mma16816(acc[mt][j * 2 + 1], a[mt], b[2], b[3]);
            }
        }
    }
}

__device__ __forceinline__ void gemm_mainloop(uint32_t sb, int tid, int lane, int wm, int wn,
                                              const __half* __restrict__ A, int a_ld,
                                              const int* rows,
                                              const __half* __restrict__ B, int b_ld,
                                              int n0, int NCH, float acc[4][4][4]) {
#pragma unroll
    for (int s = 0; s < STAGES - 1; s++) {
        fill_tiles(sb + OFF_TILE + s * BUF_SZ, tid, A, a_ld, rows, B, b_ld, n0, s * KC);
        CP_COMMIT();
    }
    int stage = 0;
    for (int c = 0; c < NCH; c++) {
        if (c + 1 < NCH) CP_WAIT1(); else CP_WAIT0();
        __syncthreads();
        if (c + STAGES - 1 < NCH) {
            int fs = stage + STAGES - 1; if (fs >= STAGES) fs -= STAGES;
            fill_tiles(sb + OFF_TILE + fs * BUF_SZ, tid, A, a_ld, rows, B, b_ld, n0,
                       (c + STAGES - 1) * KC);
            CP_COMMIT();
        }
        compute_chunk(sb + OFF_TILE + stage * BUF_SZ, lane, wm, wn, acc);
        stage++; if (stage >= STAGES) stage = 0;
    }
}

// tile-count prefix over experts; returns total, fills pre[NE+1]
__device__ __forceinline__ int tile_prefix(int nn, int* pre) {
    int total = 0;
#pragma unroll
    for (int e = 0; e < NE; e++) {
        pre[e] = total;
        total += ((g_cnt[e] + BM - 1) / BM) * nn;
    }
    pre[NE] = total;
    return total;
}

// ---------------- FC1 (persistent tiles): h[hrow] = relu(x@w1 + b1) -> fp16 ----------------
__global__ void __launch_bounds__(256, 2)
k_fc1(const float* __restrict__ b1) {
    extern __shared__ char smem[];
    uint32_t sb = smem_u32(smem);
    int tid = threadIdx.x, wid = tid >> 5, lane = tid & 31;
    int* toks  = (int*)(smem + OFF_TOK);
    int* hrows = (int*)(smem + OFF_HR);
    int wm = (wid >> 2) * 64, wn = (wid & 3) * 32;

    int pre[NE + 1];
    int total = tile_prefix(NN1, pre);

    for (int t = blockIdx.x; t < total; t += gridDim.x) {
        int e = 0;
#pragma unroll
        for (int q = 0; q < NE - 1; q++) if (t >= pre[q + 1]) e = q + 1;
        int local = t - pre[e];
        int m0 = (local >> 5) * BM;          // NN1 = 32
        int n0 = (local & 31) * BN;
        int cnt = g_cnt[e];

        __syncthreads();   // all warps done with prior tile's smem reads
        if (tid < BM) {
            int s = m0 + tid;
            toks [tid] = (s < cnt) ? g_tok [e * NT + s] : -1;
            hrows[tid] = (s < cnt) ? g_hrow[e * NT + s] : -1;
        }
        __syncthreads();

        const __half* W = g_w1f + (size_t)e * DD * HH;
        float acc[4][4][4];
#pragma unroll
        for (int a = 0; a < 4; a++)
#pragma unroll
            for (int b = 0; b < 4; b++)
#pragma unroll
                for (int c = 0; c < 4; c++) acc[a][b][c] = 0.0f;

        gemm_mainloop(sb, tid, lane, wm, wn, g_xf, DD, toks, W, HH, n0, DD / KC, acc);

        const float* bb = b1 + (size_t)e * HH + n0;
#pragma unroll
        for (int mt = 0; mt < 4; mt++) {
#pragma unroll
            for (int nt = 0; nt < 4; nt++) {
                int col = wn + nt * 8 + (lane & 3) * 2;
                float bv0 = bb[col], bv1 = bb[col + 1];
#pragma unroll
                for (int half = 0; half < 2; half++) {
                    int li = wm + mt * 16 + (lane >> 2) + half * 8;
                    int hr = hrows[li];
                    if (hr < 0) continue;
                    float h0 = fmaxf(acc[mt][nt][half * 2 + 0] + bv0, 0.0f);
                    float h1 = fmaxf(acc[mt][nt][half * 2 + 1] + bv1, 0.0f);
                    __half2 hp = __floats2half2_rn(h0, h1);
                    *(uint32_t*)(g_hf + (size_t)hr * HH + n0 + col) = *(uint32_t*)&hp;
                }
            }
        }
    }
}

// ---------------- FC2 (persistent tiles): out += gate * (h@w2 + b2) via RED ----------------
__global__ void __launch_bounds__(256, 2)
k_fc2(const float* __restrict__ b2, float* __restrict__ out) {
    extern __shared__ char smem[];
    uint32_t sb = smem_u32(smem);
    int tid = threadIdx.x, wid = tid >> 5, lane = tid & 31;
    int*   toks  = (int*)(smem + OFF_TOK);
    int*   hrows = (int*)(smem + OFF_HR);
    float* gws   = (float*)(smem + OFF_GWS);
    int wm = (wid >> 2) * 64, wn = (wid & 3) * 32;

    int pre[NE + 1];
    int total = tile_prefix(NN2, pre);

    for (int t = blockIdx.x; t < total; t += gridDim.x) {
        int e = 0;
#pragma unroll
        for (int q = 0; q < NE - 1; q++) if (t >= pre[q + 1]) e = q + 1;
        int local = t - pre[e];
        int m0 = (local >> 3) * BM;          // NN2 = 8
        int n0 = (local & 7) * BN;
        int cnt = g_cnt[e];

        __syncthreads();
        if (tid < BM) {
            int s = m0 + tid;
            toks [tid] = (s < cnt) ? g_tok [e * NT + s] : -1;
            hrows[tid] = (s < cnt) ? g_hrow[e * NT + s] : -1;
            gws  [tid] = (s < cnt) ? g_gw  [e * NT + s] : 0.0f;
        }
        __syncthreads();

        const __half* W = g_w2f + (size_t)e * HH * DD;
        float acc[4][4][4];
#pragma unroll
        for (int a = 0; a < 4; a++)
#pragma unroll
            for (int b = 0; b < 4; b++)
#pragma unroll
                for (int c = 0; c < 4; c++) acc[a][b][c] = 0.0f;

        gemm_mainloop(sb, tid, lane, wm, wn, g_hf, HH, hrows, W, DD, n0, HH / KC, acc);

        const float* bb = b2 + (size_t)e * DD + n0;
#pragma unroll
        for (int mt = 0; mt < 4; mt++) {
#pragma unroll
            for (int nt = 0; nt < 4; nt++) {
                int col = wn + nt * 8 + (lane & 3) * 2;
                float bv0 = bb[col], bv1 = bb[col + 1];
#pragma unroll
                for (int half = 0; half < 2; half++) {
                    int li = wm + mt * 16 + (lane >> 2) + half * 8;
                    int tok = toks[li];
                    if (tok < 0) continue;
                    float g = gws[li];
                    float* op = out + (size_t)tok * DD + n0 + col;
                    red_add(op + 0, g * (acc[mt][nt][half * 2 + 0] + bv0));
                    red_add(op + 1, g * (acc[mt][nt][half * 2 + 1] + bv1));
                }
            }
        }
    }
}

// ---------------- launch ----------------
extern "C" void kernel_launch(void* const* d_in, const int* in_sizes, int n_in,
                              void* d_out, int out_size) {
    const float* x  = (const float*)d_in[0];
    const float* gw = (const float*)d_in[1];
    const float* gb = (const float*)d_in[2];
    const float* w1 = (const float*)d_in[3];
    const float* b1 = (const float*)d_in[4];
    const float* w2 = (const float*)d_in[5];
    const float* b2 = (const float*)d_in[6];
    float* out = (float*)d_out;

    cudaFuncSetAttribute(k_fc1, cudaFuncAttributeMaxDynamicSharedMemorySize, SMEM_SZ);
    cudaFuncSetAttribute(k_fc2, cudaFuncAttributeMaxDynamicSharedMemorySize, SMEM_SZ);

    int nsm = 148;
    cudaDeviceGetAttribute(&nsm, cudaDevAttrMultiProcessorCount, 0);
    int ngrid = 2 * nsm;   // exactly fills the co-resident slots (2 CTAs/SM)

    void* cntp; cudaGetSymbolAddress(&cntp, g_cnt);
    cudaMemsetAsync(cntp, 0, NE * sizeof(int));
    cudaMemsetAsync(out, 0, (size_t)out_size * sizeof(float));

    k_prepass<<<NB_TOTAL, 256>>>(x, gw, gb, w1, w2);

    k_fc1<<<ngrid, 256, SMEM_SZ>>>(b1);
    k_fc2<<<ngrid, 256, SMEM_SZ>>>(b2, out);
}